// round 10
// baseline (speedup 1.0000x reference)
#include <cuda_runtime.h>
#include <math.h>

// ---------------------------------------------------------------------------
// Problem constants
// ---------------------------------------------------------------------------
#define R_RAYS   8192
#define S_SAMP   64
#define NSAMP    (R_RAYS * S_SAMP)      // 524288
#define C_FEAT   32
#define NTILES   (NSAMP / 128)          // 4096

__device__ __constant__ int d_J[6] = {0,0,0,1,1,2};
__device__ __constant__ int d_K[6] = {1,2,3,2,3,3};

__device__ __constant__ int d_cw[6]    = {64,64,50,64,50,50};
__device__ __constant__ int d_cbase[6] = {0,4096,8192,11392,15488,18688};
#define N_COARSE 21888

__device__ __constant__ int d_fw[6]    = {128,128,100,128,100,100};
__device__ __constant__ int d_fbase[6] = {0,16384,32768,45568,61952,74752};
#define N_FINE 87552

// ---------------------------------------------------------------------------
// Scratch (device globals; no runtime allocation allowed)
// ---------------------------------------------------------------------------
__device__ float g_hi[N_FINE * C_FEAT];
__device__ float g_lo[N_FINE * C_FEAT];
__device__ float g_enc[R_RAYS * 16];

// ---------------------------------------------------------------------------
// tf32 helpers
// ---------------------------------------------------------------------------
__device__ __forceinline__ unsigned tf32_bits(float x) {
    unsigned u;
    asm("cvt.rna.tf32.f32 %0, %1;" : "=r"(u) : "f"(x));
    return u;
}
__device__ __forceinline__ float tf32_val(float x) {
    return __uint_as_float(tf32_bits(x));
}

__device__ __forceinline__ void mma_tf32(float* d,
    unsigned a0, unsigned a1, unsigned a2, unsigned a3,
    unsigned b0, unsigned b1)
{
    asm volatile(
        "mma.sync.aligned.m16n8k8.row.col.f32.tf32.tf32.f32 "
        "{%0,%1,%2,%3}, {%4,%5,%6,%7}, {%8,%9}, {%0,%1,%2,%3};"
        : "+f"(d[0]), "+f"(d[1]), "+f"(d[2]), "+f"(d[3])
        : "r"(a0), "r"(a1), "r"(a2), "r"(a3), "r"(b0), "r"(b1));
}

#define BARX(id, cnt) asm volatile("bar.sync %0, %1;" :: "r"(id), "r"(cnt) : "memory")

// ---------------------------------------------------------------------------
// Kernel 1: expand (yl, yh) -> hi / lo fine planes
// ---------------------------------------------------------------------------
__global__ void expand_kernel(
    const float* __restrict__ yl0, const float* __restrict__ yh0,
    const float* __restrict__ yl1, const float* __restrict__ yh1,
    const float* __restrict__ yl2, const float* __restrict__ yh2,
    const float* __restrict__ yl3, const float* __restrict__ yh3,
    const float* __restrict__ yl4, const float* __restrict__ yh4,
    const float* __restrict__ yl5, const float* __restrict__ yh5)
{
    const float* yls[6] = {yl0, yl1, yl2, yl3, yl4, yl5};
    const float* yhs[6] = {yh0, yh1, yh2, yh3, yh4, yh5};

    int warpIdx = (blockIdx.x * blockDim.x + threadIdx.x) >> 5;
    int lane    = threadIdx.x & 31;
    if (warpIdx >= N_COARSE) return;

    int p = 0;
    #pragma unroll
    for (int q = 1; q < 6; q++) if (warpIdx >= d_cbase[q]) p = q;

    int local = warpIdx - d_cbase[p];
    int w  = d_cw[p];
    int cy = local / w;
    int cx = local - cy * w;
    int hw = 64 * w;

    const float* yl = yls[p];
    const float* yh = yhs[p];

    float a  = yl[lane * hw + cy * w + cx];
    const float* yhc = yh + (size_t)lane * 3 * hw + cy * w + cx;
    float lh = yhc[0];
    float hl = yhc[hw];
    float hh = yhc[2 * hw];

    int W    = 2 * w;
    int base = d_fbase[p] + (2 * cy) * W + 2 * cx;
    int i00 = base * 32 + lane;
    int i01 = i00 + 32;
    int i10 = (base + W) * 32 + lane;
    int i11 = i10 + 32;

    g_hi[i00] = 0.5f * (a + lh + hl + hh);
    g_hi[i01] = 0.5f * (a + lh - hl - hh);
    g_hi[i10] = 0.5f * (a - lh + hl - hh);
    g_hi[i11] = 0.5f * (a - lh - hl + hh);

    float lv = 0.5f * a;
    g_lo[i00] = lv; g_lo[i01] = lv; g_lo[i10] = lv; g_lo[i11] = lv;
}

// ---------------------------------------------------------------------------
// Kernel 2: SH degree-4 encoding per ray
// ---------------------------------------------------------------------------
__global__ void sh_kernel(const float* __restrict__ dirs)
{
    int r = blockIdx.x * blockDim.x + threadIdx.x;
    if (r >= R_RAYS) return;
    float dx = dirs[3*r], dy = dirs[3*r+1], dz = dirs[3*r+2];
    float nrm = sqrtf(dx*dx + dy*dy + dz*dz);
    float x = dx / nrm, y = dy / nrm, z = dz / nrm;
    float xx = x*x, yy = y*y, zz = z*z;

    float* e = g_enc + r * 16;
    e[0]  = 0.28209479177387814f;
    e[1]  = -0.4886025119029199f * y;
    e[2]  =  0.4886025119029199f * z;
    e[3]  = -0.4886025119029199f * x;
    e[4]  =  1.0925484305920792f * x * y;
    e[5]  = -1.0925484305920792f * y * z;
    e[6]  =  0.31539156525252005f * (3.0f * zz - 1.0f);
    e[7]  = -1.0925484305920792f * x * z;
    e[8]  =  0.5462742152960396f * (xx - yy);
    e[9]  = -0.5900435899266435f * y * (3.0f * xx - yy);
    e[10] =  2.890611442640554f * x * y * z;
    e[11] = -0.4570457994644658f * y * (5.0f * zz - 1.0f);
    e[12] =  0.3731763325901154f * z * (5.0f * zz - 3.0f);
    e[13] = -0.4570457994644658f * x * (5.0f * zz - 1.0f);
    e[14] =  1.445305721320277f * z * (xx - yy);
    e[15] = -0.5900435899266435f * x * (xx - 3.0f * yy);
}

// ---------------------------------------------------------------------------
// Fused kernel: warp-specialized gather (4 producer warps) + tensor-core MLP
// (8 consumer warps).  384 threads, persistent grid, gridDim-strided tiles.
//
// smem float offsets:
//   weights:  W1B@0 W1S@4608 W2B@9216 W2S@10752 C1B@12288 C1S@14592
//             C2B@16896 C2S@21504 C3@26112  DENS@26336 (128)
//   F @26496  [64][136]  feats tile (producer-written)
//   A @35200  [64][136]  MLP buffer A
//   B @43904  [64][136]  MLP buffer B
//   total 52608 floats = 210432 B  -> 1 block/SM, 12 warps.
//
// Pipeline per block (bar 3 = "F holds tile t", bar 4 = "L1 reads done"):
//   producers gather tile(t+stride) between bar4(t) and bar3(t+1).
// Consumer-internal stage syncs use bar.sync 5,256 (warps 0-7 only).
// ---------------------------------------------------------------------------
#define O_W1B   0
#define O_W1S   4608
#define O_W2B   9216
#define O_W2S   10752
#define O_C1B   12288
#define O_C1S   14592
#define O_C2B   16896
#define O_C2S   21504
#define O_C3    26112
#define O_DENS  26336
#define O_F     26496
#define O_A     35200
#define O_B     43904
#define MLP_SMEM (52608 * 4)
#define MLP_THREADS 384
#define MLP_GRID 148

// GEMM: D[128 samples x n-range] = act(K x s) * W(K x n), 3xTF32.
template<int NK, int NTW>
__device__ __forceinline__ void gemm3x(const float* __restrict__ act,
                                       const float* __restrict__ wb,
                                       const float* __restrict__ ws,
                                       int wstr, int nbase,
                                       int lane, int wm,
                                       float (&d)[2][NTW][4])
{
    #pragma unroll
    for (int mt = 0; mt < 2; mt++)
        #pragma unroll
        for (int nt = 0; nt < NTW; nt++)
            #pragma unroll
            for (int r = 0; r < 4; r++) d[mt][nt][r] = 0.0f;

    const int srow = wm * 32 + (lane >> 2);
    const int kcol = lane & 3;
    const int ncol = lane >> 2;

    #pragma unroll
    for (int kk = 0; kk < NK; kk++) {
        unsigned ab[2][4], as[2][4];
        #pragma unroll
        for (int mt = 0; mt < 2; mt++) {
            const float* ap = act + (kk * 8 + kcol) * 136 + srow + mt * 16;
            float r0 = ap[0];
            float r1 = ap[8];
            float r2 = ap[4 * 136];
            float r3 = ap[4 * 136 + 8];
            ab[mt][0] = tf32_bits(r0);
            ab[mt][1] = tf32_bits(r1);
            ab[mt][2] = tf32_bits(r2);
            ab[mt][3] = tf32_bits(r3);
            as[mt][0] = tf32_bits(r0 - __uint_as_float(ab[mt][0]));
            as[mt][1] = tf32_bits(r1 - __uint_as_float(ab[mt][1]));
            as[mt][2] = tf32_bits(r2 - __uint_as_float(ab[mt][2]));
            as[mt][3] = tf32_bits(r3 - __uint_as_float(ab[mt][3]));
        }
        const float* wpb = wb + (kk * 8 + kcol) * wstr + ncol + nbase;
        const float* wps = ws + (kk * 8 + kcol) * wstr + ncol + nbase;
        #pragma unroll
        for (int nt = 0; nt < NTW; nt++) {
            unsigned bb0 = __float_as_uint(wpb[nt * 8]);
            unsigned bb1 = __float_as_uint(wpb[4 * wstr + nt * 8]);
            unsigned bs0 = __float_as_uint(wps[nt * 8]);
            unsigned bs1 = __float_as_uint(wps[4 * wstr + nt * 8]);
            #pragma unroll
            for (int mt = 0; mt < 2; mt++) {
                mma_tf32(d[mt][nt], ab[mt][0], ab[mt][1], ab[mt][2], ab[mt][3], bb0, bb1);
                mma_tf32(d[mt][nt], as[mt][0], as[mt][1], as[mt][2], as[mt][3], bb0, bb1);
                mma_tf32(d[mt][nt], ab[mt][0], ab[mt][1], ab[mt][2], ab[mt][3], bs0, bs1);
            }
        }
    }
}

template<int NTW>
__device__ __forceinline__ void store_relu(float* __restrict__ dst,
                                           int nbase, int lane, int wm,
                                           float (&d)[2][NTW][4])
{
    int s0 = wm * 32 + (lane >> 2);
    int nb = 2 * (lane & 3);
    #pragma unroll
    for (int mt = 0; mt < 2; mt++) {
        int s = s0 + mt * 16;
        #pragma unroll
        for (int nt = 0; nt < NTW; nt++) {
            int n = nbase + nt * 8 + nb;
            dst[n * 136 + s]           = fmaxf(d[mt][nt][0], 0.0f);
            dst[(n + 1) * 136 + s]     = fmaxf(d[mt][nt][1], 0.0f);
            dst[n * 136 + s + 8]       = fmaxf(d[mt][nt][2], 0.0f);
            dst[(n + 1) * 136 + s + 8] = fmaxf(d[mt][nt][3], 0.0f);
        }
    }
}

// Producer: warp wp (0..3) gathers samples [tile*128 + wp*32, +32) into F.
__device__ __forceinline__ void gather_to_F(
    float* __restrict__ F, int tile, int wp, int lane,
    const float* __restrict__ pts, const float* __restrict__ tstamps)
{
    int n = tile * 128 + wp * 32 + lane;

    float p4[4];
    p4[0] = pts[3*n + 0];
    p4[1] = pts[3*n + 1];
    p4[2] = pts[3*n + 2];
    p4[3] = tstamps[n >> 6] * 2.0f - 1.0f;

    int   A0r[6], A1r[6], A2r[6], A3r[6];
    float WY[6], WX[6];

    #pragma unroll
    for (int m = 0; m < 6; m++) {
        float cy_ = p4[d_J[m]];
        float cx_ = p4[d_K[m]];
        int W = d_fw[m];

        float y = (cy_ + 1.0f) * 0.5f * 127.0f;
        float x = (cx_ + 1.0f) * 0.5f * (float)(W - 1);

        float fy = floorf(y);
        int y0 = (int)fminf(fmaxf(fy, 0.0f), 127.0f);
        float wy = fminf(fmaxf(y - (float)y0, 0.0f), 1.0f);
        int y1 = min(y0 + 1, 127);

        float fx = floorf(x);
        int x0 = (int)fminf(fmaxf(fx, 0.0f), (float)(W - 1));
        float wx = fminf(fmaxf(x - (float)x0, 0.0f), 1.0f);
        int x1 = min(x0 + 1, W - 1);

        int b = d_fbase[m];
        A0r[m] = (b + y0 * W + x0) * 32;
        A1r[m] = (b + y0 * W + x1) * 32;
        A2r[m] = (b + y1 * W + x0) * 32;
        A3r[m] = (b + y1 * W + x1) * 32;
        WY[m] = wy;
        WX[m] = wx;
    }

    for (int i = 0; i < 32; i++) {
        float ah = 1.0f, al = 1.0f;
        #pragma unroll
        for (int m = 0; m < 6; m++) {
            int a00 = __shfl_sync(0xffffffffu, A0r[m], i);
            int a01 = __shfl_sync(0xffffffffu, A1r[m], i);
            int a10 = __shfl_sync(0xffffffffu, A2r[m], i);
            int a11 = __shfl_sync(0xffffffffu, A3r[m], i);
            float wy = __shfl_sync(0xffffffffu, WY[m], i);
            float wx = __shfl_sync(0xffffffffu, WX[m], i);
            float w00 = (1.0f - wy) * (1.0f - wx);
            float w01 = (1.0f - wy) * wx;
            float w10 = wy * (1.0f - wx);
            float w11 = wy * wx;

            float vh = w00 * __ldg(g_hi + a00 + lane)
                     + w01 * __ldg(g_hi + a01 + lane)
                     + w10 * __ldg(g_hi + a10 + lane)
                     + w11 * __ldg(g_hi + a11 + lane);
            float vl = w00 * __ldg(g_lo + a00 + lane)
                     + w01 * __ldg(g_lo + a01 + lane)
                     + w10 * __ldg(g_lo + a10 + lane)
                     + w11 * __ldg(g_lo + a11 + lane);
            ah *= vh;
            al *= vl;
        }
        int s = wp * 32 + i;
        F[lane * 136 + s]        = ah;   // hi features: rows 0..31
        F[(32 + lane) * 136 + s] = al;   // lo features: rows 32..63
    }
}

__global__ void __launch_bounds__(MLP_THREADS) fused_kernel(
    const float* __restrict__ pts, const float* __restrict__ tstamps,
    const float* __restrict__ Ws1, const float* __restrict__ Ws2,
    const float* __restrict__ Wc1, const float* __restrict__ Wc2,
    const float* __restrict__ Wc3, float* __restrict__ out)
{
    extern __shared__ __align__(16) float sm[];
    const int tid  = threadIdx.x;
    const int lane = tid & 31;
    const int warp = tid >> 5;
    const int wm   = warp & 3;          // consumer m-quarter
    const int wg   = warp >> 2;         // consumer n-half (0/1 for warps 0-7)

    // ---- stage weights once per block (tf32 big/small split) ----
    for (int i = tid; i < 4096; i += MLP_THREADS) {
        int k = i >> 6, n = i & 63;
        float w = Ws1[i];
        float b = tf32_val(w);
        sm[O_W1B + k * 72 + n] = b;
        sm[O_W1S + k * 72 + n] = tf32_val(w - b);
        float w2 = Wc2[i];
        float b2 = tf32_val(w2);
        sm[O_C2B + k * 72 + n] = b2;
        sm[O_C2S + k * 72 + n] = tf32_val(w2 - b2);
    }
    for (int i = tid; i < 1024; i += MLP_THREADS) {
        int k = i >> 4, n = i & 15;
        float w = Ws2[i];
        float b = tf32_val(w);
        sm[O_W2B + k * 24 + n] = b;
        sm[O_W2S + k * 24 + n] = tf32_val(w - b);
    }
    for (int i = tid; i < 1984; i += MLP_THREADS) {
        int k = i >> 6, n = i & 63;
        float w = Wc1[i];
        float b = tf32_val(w);
        sm[O_C1B + k * 72 + n] = b;
        sm[O_C1S + k * 72 + n] = tf32_val(w - b);
    }
    if (tid < 72) {
        sm[O_C1B + 31 * 72 + tid] = 0.0f;
        sm[O_C1S + 31 * 72 + tid] = 0.0f;
    }
    for (int i = tid; i < 192; i += MLP_THREADS) sm[O_C3 + i] = Wc3[i];
    __syncthreads();

    int tile = blockIdx.x;
    const int stride = gridDim.x;

    // prologue: producers gather first tile
    if (warp >= 8 && tile < NTILES)
        gather_to_F(sm + O_F, tile, warp - 8, lane, pts, tstamps);

    for (; tile < NTILES; tile += stride) {
        BARX(3, MLP_THREADS);           // F holds tile's feats

        float d1[2][4][4];
        if (warp < 8) {
            // ===== L1: feats(F) @ Wsig1 =====
            gemm3x<8, 4>(sm + O_F, sm + O_W1B, sm + O_W1S, 72, wg * 32, lane, wm, d1);
        }

        BARX(4, MLP_THREADS);           // all L1 reads of F done

        if (warp < 8) {
            const int base = tile * 128;

            store_relu<4>(sm + O_B, wg * 32, lane, wm, d1);
            // fill SC1 input rows 0..15 (SH enc) and row 31 (zero) in A
            for (int i = tid; i < 2048; i += 256) {
                int j = i >> 7, s = i & 127;
                sm[O_A + j * 136 + s] = __ldg(g_enc + (tile * 2 + (s >> 6)) * 16 + j);
            }
            if (tid < 128) sm[O_A + 31 * 136 + tid] = 0.0f;
            BARX(5, 256);

            // ===== L2: h(B) @ Wsig2 -> geo rows 16..30 of A, density =====
            {
                float d[2][1][4];
                gemm3x<8, 1>(sm + O_B, sm + O_W2B, sm + O_W2S, 24, wg * 8, lane, wm, d);
                int s0 = wm * 32 + (lane >> 2);
                int nb = 2 * (lane & 3);
                #pragma unroll
                for (int mt = 0; mt < 2; mt++) {
                    int s = s0 + mt * 16;
                    int n = wg * 8 + nb;
                    #pragma unroll
                    for (int r = 0; r < 4; r++) {
                        int nn = n + (r & 1);
                        int ss = s + (r >> 1) * 8;
                        float v = d[mt][0][r];
                        if (nn == 15)
                            sm[O_DENS + ss] = expf(fminf(fmaxf(v, -15.0f), 15.0f));
                        else
                            sm[O_A + (16 + nn) * 136 + ss] = v;
                    }
                }
                BARX(5, 256);
            }

            // ===== SC1: ci(A) @ Wc1 -> relu -> B =====
            {
                float d[2][4][4];
                gemm3x<4, 4>(sm + O_A, sm + O_C1B, sm + O_C1S, 72, wg * 32, lane, wm, d);
                BARX(5, 256);
                store_relu<4>(sm + O_B, wg * 32, lane, wm, d);
                BARX(5, 256);
            }

            // ===== SC2: h(B) @ Wc2 -> relu -> A =====
            {
                float d[2][4][4];
                gemm3x<8, 4>(sm + O_B, sm + O_C2B, sm + O_C2S, 72, wg * 32, lane, wm, d);
                BARX(5, 256);
                store_relu<4>(sm + O_A, wg * 32, lane, wm, d);
                BARX(5, 256);
            }

            // ===== SC3: h(A) @ Wc3 -> sigmoid rgb + density =====
            if (tid < 128) {
                float a0 = 0.f, a1 = 0.f, a2 = 0.f;
                #pragma unroll 8
                for (int k = 0; k < 64; k++) {
                    float h = sm[O_A + k * 136 + tid];
                    a0 += h * sm[O_C3 + k * 3];
                    a1 += h * sm[O_C3 + k * 3 + 1];
                    a2 += h * sm[O_C3 + k * 3 + 2];
                }
                float4 o;
                o.x = 1.0f / (1.0f + expf(-a0));
                o.y = 1.0f / (1.0f + expf(-a1));
                o.z = 1.0f / (1.0f + expf(-a2));
                o.w = sm[O_DENS + tid];
                ((float4*)out)[base + tid] = o;
            }
        } else {
            // producers: gather next tile while consumers run the MLP tail
            int nt = tile + stride;
            if (nt < NTILES)
                gather_to_F(sm + O_F, nt, warp - 8, lane, pts, tstamps);
        }
    }
}

// ---------------------------------------------------------------------------
// Launch
// ---------------------------------------------------------------------------
extern "C" void kernel_launch(void* const* d_in, const int* in_sizes, int n_in,
                              void* d_out, int out_size)
{
    const float* pts   = (const float*)d_in[0];
    const float* dirs  = (const float*)d_in[1];
    const float* ts    = (const float*)d_in[2];
    const float* yl[6], *yh[6];
    for (int i = 0; i < 6; i++) {
        yl[i] = (const float*)d_in[3 + 2*i];
        yh[i] = (const float*)d_in[4 + 2*i];
    }
    const float* Ws1 = (const float*)d_in[15];
    const float* Ws2 = (const float*)d_in[16];
    const float* Wc1 = (const float*)d_in[17];
    const float* Wc2 = (const float*)d_in[18];
    const float* Wc3 = (const float*)d_in[19];
    float* out = (float*)d_out;

    static bool attr_done = false;
    if (!attr_done) {
        cudaFuncSetAttribute(fused_kernel,
                             cudaFuncAttributeMaxDynamicSharedMemorySize,
                             MLP_SMEM);
        attr_done = true;
    }

    expand_kernel<<<(N_COARSE + 7) / 8, 256>>>(
        yl[0], yh[0], yl[1], yh[1], yl[2], yh[2],
        yl[3], yh[3], yl[4], yh[4], yl[5], yh[5]);

    sh_kernel<<<R_RAYS / 256, 256>>>(dirs);

    fused_kernel<<<MLP_GRID, MLP_THREADS, MLP_SMEM>>>(
        pts, ts, Ws1, Ws2, Wc1, Wc2, Wc3, out);
}